// round 3
// baseline (speedup 1.0000x reference)
#include <cuda_runtime.h>
#include <cuda_bf16.h>

#define RED_BLOCKS 1184          // 148 SMs * 8
#define RED_THREADS 256

__device__ float g_partials[RED_BLOCKS];
__device__ unsigned int g_ticket;   // zero-initialized; atomicInc wraps back to 0

__global__ void __launch_bounds__(RED_THREADS)
qsum_fused_kernel(const float* __restrict__ phi,
                  const float* __restrict__ w,
                  int n, int nblocks,
                  float add_const, float inv_m,
                  float* __restrict__ out)
{
    const int n4 = n >> 2;
    const float4* __restrict__ p4 = reinterpret_cast<const float4*>(phi);
    const float4* __restrict__ w4 = reinterpret_cast<const float4*>(w);

    const int stride = gridDim.x * blockDim.x;
    int i = blockIdx.x * blockDim.x + threadIdx.x;

    float acc0 = 0.0f, acc1 = 0.0f;

    // main loop: 2 independent float4-pair iterations in flight
    for (; i + stride < n4; i += 2 * stride) {
        float4 pa = p4[i];
        float4 qa = w4[i];
        float4 pb = p4[i + stride];
        float4 qb = w4[i + stride];
        acc0 += __cosf(pa.x * qa.x);
        acc0 += __cosf(pa.y * qa.y);
        acc0 += __cosf(pa.z * qa.z);
        acc0 += __cosf(pa.w * qa.w);
        acc1 += __cosf(pb.x * qb.x);
        acc1 += __cosf(pb.y * qb.y);
        acc1 += __cosf(pb.z * qb.z);
        acc1 += __cosf(pb.w * qb.w);
    }
    // remainder (at most one vector iteration per thread)
    for (; i < n4; i += stride) {
        float4 p = p4[i];
        float4 q = w4[i];
        acc0 += __cosf(p.x * q.x);
        acc0 += __cosf(p.y * q.y);
        acc0 += __cosf(p.z * q.z);
        acc0 += __cosf(p.w * q.w);
    }

    // scalar tail (n % 4 elements)
    int tail = n - (n4 << 2);
    int gtid = blockIdx.x * blockDim.x + threadIdx.x;
    if (gtid < tail) {
        int idx = (n4 << 2) + gtid;
        acc0 += __cosf(phi[idx] * w[idx]);
    }

    float acc = acc0 + acc1;

    // warp reduce
    #pragma unroll
    for (int off = 16; off > 0; off >>= 1)
        acc += __shfl_down_sync(0xFFFFFFFFu, acc, off);

    __shared__ float s_warp[RED_THREADS / 32];
    int lane = threadIdx.x & 31;
    int wid  = threadIdx.x >> 5;
    if (lane == 0) s_warp[wid] = acc;
    __syncthreads();

    __shared__ bool s_last;
    if (threadIdx.x == 0) {
        float v = 0.0f;
        #pragma unroll
        for (int k = 0; k < RED_THREADS / 32; k++) v += s_warp[k];
        g_partials[blockIdx.x] = v;
        __threadfence();
        // atomicInc wraps to 0 when old == nblocks-1 -> counter self-resets
        unsigned int t = atomicInc(&g_ticket, (unsigned int)(nblocks - 1));
        s_last = (t == (unsigned int)(nblocks - 1));
    }
    __syncthreads();

    if (s_last) {
        // last block: deterministic fixed-order reduction of partials in double
        __shared__ double s_red[RED_THREADS / 32];
        double v = 0.0;
        for (int k = threadIdx.x; k < nblocks; k += RED_THREADS)
            v += (double)g_partials[k];
        #pragma unroll
        for (int off = 16; off > 0; off >>= 1)
            v += __shfl_down_sync(0xFFFFFFFFu, v, off);
        if (lane == 0) s_red[wid] = v;
        __syncthreads();
        if (wid == 0) {
            double x = (lane < RED_THREADS / 32) ? s_red[lane] : 0.0;
            #pragma unroll
            for (int off = 4; off > 0; off >>= 1)
                x += __shfl_down_sync(0xFFFFFFFFu, x, off);
            if (lane == 0)
                out[0] = (float)((x + (double)add_const) * (double)inv_m);
        }
    }
}

extern "C" void kernel_launch(void* const* d_in, const int* in_sizes, int n_in,
                              void* d_out, int out_size)
{
    const float* phi = (const float*)d_in[0];
    const float* w   = (const float*)d_in[1];
    float* out = (float*)d_out;
    int n = in_sizes[0];

    long long M = 1;
    while (M < (long long)n) M <<= 1;
    float add_const = (float)(M - (long long)n);
    float inv_m = (float)(1.0 / (double)M);

    int blocks = RED_BLOCKS;
    long long work4 = (n >> 2);
    if (work4 < (long long)blocks * RED_THREADS) {
        blocks = (int)((work4 + RED_THREADS - 1) / RED_THREADS);
        if (blocks < 1) blocks = 1;
    }

    qsum_fused_kernel<<<blocks, RED_THREADS>>>(phi, w, n, blocks,
                                               add_const, inv_m, out);
}

// round 4
// speedup vs baseline: 1.0803x; 1.0803x over previous
#include <cuda_runtime.h>
#include <cuda_bf16.h>

#define RED_BLOCKS 1184          // 148 SMs * 8
#define RED_THREADS 256

__device__ float g_partials[RED_BLOCKS];
__device__ unsigned int g_ticket;   // zero-initialized; atomicInc wraps back to 0

__global__ void __launch_bounds__(RED_THREADS, 8)
qsum_fused_kernel(const float* __restrict__ phi,
                  const float* __restrict__ w,
                  int n, int nblocks,
                  float add_const, float inv_m,
                  float* __restrict__ out)
{
    const int n4 = n >> 2;
    const float4* __restrict__ p4 = reinterpret_cast<const float4*>(phi);
    const float4* __restrict__ w4 = reinterpret_cast<const float4*>(w);

    const int stride = gridDim.x * blockDim.x;
    float acc = 0.0f;

    // simple grid-stride float4 loop — lowest register pressure, full occupancy
    for (int i = blockIdx.x * blockDim.x + threadIdx.x; i < n4; i += stride) {
        float4 p = p4[i];
        float4 q = w4[i];
        acc += __cosf(p.x * q.x);
        acc += __cosf(p.y * q.y);
        acc += __cosf(p.z * q.z);
        acc += __cosf(p.w * q.w);
    }

    // scalar tail (n % 4 elements)
    int tail = n - (n4 << 2);
    int gtid = blockIdx.x * blockDim.x + threadIdx.x;
    if (gtid < tail) {
        int idx = (n4 << 2) + gtid;
        acc += __cosf(phi[idx] * w[idx]);
    }

    // warp reduce
    #pragma unroll
    for (int off = 16; off > 0; off >>= 1)
        acc += __shfl_down_sync(0xFFFFFFFFu, acc, off);

    __shared__ float s_warp[RED_THREADS / 32];
    int lane = threadIdx.x & 31;
    int wid  = threadIdx.x >> 5;
    if (lane == 0) s_warp[wid] = acc;
    __syncthreads();

    __shared__ bool s_last;
    if (threadIdx.x == 0) {
        float v = 0.0f;
        #pragma unroll
        for (int k = 0; k < RED_THREADS / 32; k++) v += s_warp[k];
        g_partials[blockIdx.x] = v;
        __threadfence();
        // atomicInc wraps to 0 when old == nblocks-1 -> counter self-resets
        unsigned int t = atomicInc(&g_ticket, (unsigned int)(nblocks - 1));
        s_last = (t == (unsigned int)(nblocks - 1));
    }
    __syncthreads();

    if (s_last) {
        // last block: deterministic fixed-order reduction of partials in double
        __shared__ double s_red[RED_THREADS / 32];
        double v = 0.0;
        for (int k = threadIdx.x; k < nblocks; k += RED_THREADS)
            v += (double)g_partials[k];
        #pragma unroll
        for (int off = 16; off > 0; off >>= 1)
            v += __shfl_down_sync(0xFFFFFFFFu, v, off);
        if (lane == 0) s_red[wid] = v;
        __syncthreads();
        if (wid == 0) {
            double x = (lane < RED_THREADS / 32) ? s_red[lane] : 0.0;
            #pragma unroll
            for (int off = 4; off > 0; off >>= 1)
                x += __shfl_down_sync(0xFFFFFFFFu, x, off);
            if (lane == 0)
                out[0] = (float)((x + (double)add_const) * (double)inv_m);
        }
    }
}

extern "C" void kernel_launch(void* const* d_in, const int* in_sizes, int n_in,
                              void* d_out, int out_size)
{
    const float* phi = (const float*)d_in[0];
    const float* w   = (const float*)d_in[1];
    float* out = (float*)d_out;
    int n = in_sizes[0];

    long long M = 1;
    while (M < (long long)n) M <<= 1;
    float add_const = (float)(M - (long long)n);
    float inv_m = (float)(1.0 / (double)M);

    int blocks = RED_BLOCKS;
    long long work4 = (n >> 2);
    if (work4 < (long long)blocks * RED_THREADS) {
        blocks = (int)((work4 + RED_THREADS - 1) / RED_THREADS);
        if (blocks < 1) blocks = 1;
    }

    qsum_fused_kernel<<<blocks, RED_THREADS>>>(phi, w, n, blocks,
                                               add_const, inv_m, out);
}

// round 5
// speedup vs baseline: 1.0816x; 1.0012x over previous
#include <cuda_runtime.h>
#include <cuda_bf16.h>

#define RED_BLOCKS 1184          // 148 SMs * 8
#define RED_THREADS 256

__device__ float g_partials[RED_BLOCKS];
__device__ unsigned int g_ticket;   // zero-initialized; atomicInc wraps back to 0

__global__ void __launch_bounds__(RED_THREADS, 8)
qsum_fused_kernel(const float* __restrict__ phi,
                  const float* __restrict__ w,
                  int n, int nblocks,
                  float add_const, float inv_m,
                  float* __restrict__ out)
{
    const int n8 = n >> 3;                       // 32-byte chunks per array
    const float4* __restrict__ p4 = reinterpret_cast<const float4*>(phi);
    const float4* __restrict__ w4 = reinterpret_cast<const float4*>(w);

    const int stride = gridDim.x * blockDim.x;
    float acc = 0.0f;

    // each iteration: 32 contiguous bytes from each array (2 adjacent float4)
    for (int i = blockIdx.x * blockDim.x + threadIdx.x; i < n8; i += stride) {
        float4 pa = __ldcs(p4 + 2 * i);
        float4 qa = __ldcs(w4 + 2 * i);
        float4 pb = __ldcs(p4 + 2 * i + 1);
        float4 qb = __ldcs(w4 + 2 * i + 1);
        acc += __cosf(pa.x * qa.x);
        acc += __cosf(pa.y * qa.y);
        acc += __cosf(pa.z * qa.z);
        acc += __cosf(pa.w * qa.w);
        acc += __cosf(pb.x * qb.x);
        acc += __cosf(pb.y * qb.y);
        acc += __cosf(pb.z * qb.z);
        acc += __cosf(pb.w * qb.w);
    }

    // scalar tail (n % 8 elements)
    int done = n8 << 3;
    int tail = n - done;
    int gtid = blockIdx.x * blockDim.x + threadIdx.x;
    if (gtid < tail) {
        int idx = done + gtid;
        acc += __cosf(phi[idx] * w[idx]);
    }

    // warp reduce
    #pragma unroll
    for (int off = 16; off > 0; off >>= 1)
        acc += __shfl_down_sync(0xFFFFFFFFu, acc, off);

    __shared__ float s_warp[RED_THREADS / 32];
    int lane = threadIdx.x & 31;
    int wid  = threadIdx.x >> 5;
    if (lane == 0) s_warp[wid] = acc;
    __syncthreads();

    __shared__ bool s_last;
    if (threadIdx.x == 0) {
        float v = 0.0f;
        #pragma unroll
        for (int k = 0; k < RED_THREADS / 32; k++) v += s_warp[k];
        g_partials[blockIdx.x] = v;
        __threadfence();
        // atomicInc wraps to 0 when old == nblocks-1 -> counter self-resets
        unsigned int t = atomicInc(&g_ticket, (unsigned int)(nblocks - 1));
        s_last = (t == (unsigned int)(nblocks - 1));
    }
    __syncthreads();

    if (s_last) {
        // last block: deterministic fixed-order reduction of partials in double
        __shared__ double s_red[RED_THREADS / 32];
        double v = 0.0;
        for (int k = threadIdx.x; k < nblocks; k += RED_THREADS)
            v += (double)g_partials[k];
        #pragma unroll
        for (int off = 16; off > 0; off >>= 1)
            v += __shfl_down_sync(0xFFFFFFFFu, v, off);
        if (lane == 0) s_red[wid] = v;
        __syncthreads();
        if (wid == 0) {
            double x = (lane < RED_THREADS / 32) ? s_red[lane] : 0.0;
            #pragma unroll
            for (int off = 4; off > 0; off >>= 1)
                x += __shfl_down_sync(0xFFFFFFFFu, x, off);
            if (lane == 0)
                out[0] = (float)((x + (double)add_const) * (double)inv_m);
        }
    }
}

extern "C" void kernel_launch(void* const* d_in, const int* in_sizes, int n_in,
                              void* d_out, int out_size)
{
    const float* phi = (const float*)d_in[0];
    const float* w   = (const float*)d_in[1];
    float* out = (float*)d_out;
    int n = in_sizes[0];

    long long M = 1;
    while (M < (long long)n) M <<= 1;
    float add_const = (float)(M - (long long)n);
    float inv_m = (float)(1.0 / (double)M);

    int blocks = RED_BLOCKS;
    long long work8 = (n >> 3);
    if (work8 < (long long)blocks * RED_THREADS) {
        blocks = (int)((work8 + RED_THREADS - 1) / RED_THREADS);
        if (blocks < 1) blocks = 1;
    }

    qsum_fused_kernel<<<blocks, RED_THREADS>>>(phi, w, n, blocks,
                                               add_const, inv_m, out);
}